// round 8
// baseline (speedup 1.0000x reference)
#include <cuda_runtime.h>
#include <cuda_fp16.h>
#include <math.h>
#include <stdint.h>

#define N_NODES 50000
#define N_EDGES 300000
#define DIM 256
#define N_RELS 500

// ---------------------------------------------------------------------------
// Device-global scratch (never passed from host — R1 lesson: host reference to
// a __device__ symbol binds the host shadow array; GB300 ATS reads it as junk)
// ---------------------------------------------------------------------------
__device__ float  g_pre[N_NODES * DIM];    // fp32 segment-sum target (atomics)
__device__ int    g_indeg[N_NODES];
// fp16 hi/lo split copies of the three A operands (lossless to ~2^-22)
__device__ __half g_h_hi [N_NODES * DIM];
__device__ __half g_h_lo [N_NODES * DIM];
__device__ __half g_p_hi [N_NODES * DIM];
__device__ __half g_p_lo [N_NODES * DIM];
__device__ __half g_pre_hi[N_NODES * DIM]; // (pre * norm) hi/lo
__device__ __half g_pre_lo[N_NODES * DIM];
__device__ __half g_gate16[N_NODES * DIM]; // sigmoid(prev@Ws+b), fp16
// weights, transposed to [n][k] (K-major per output column), fp16
__device__ __half g_w1T[256 * 512];        // [Wn ; L]^T
__device__ __half g_w2T[256 * 256];        // Ws^T

// ---------------------------------------------------------------------------
// helpers
// ---------------------------------------------------------------------------
__device__ __forceinline__ uint32_t smem_u32(const void* p) {
    uint32_t a;
    asm("{ .reg .u64 t; cvta.to.shared.u64 t, %1; cvt.u32.u64 %0, t; }"
        : "=r"(a) : "l"(p));
    return a;
}
#define SWZ(o) ((o) ^ (((o) >> 3) & 0x70))

#define LDSM4(r0, r1, r2, r3, addr) \
    asm volatile("ldmatrix.sync.aligned.m8n8.x4.shared.b16 {%0,%1,%2,%3}, [%4];" \
                 : "=r"(r0), "=r"(r1), "=r"(r2), "=r"(r3) : "r"(addr))

#define MMA16816(c, a, b0, b1) \
    asm volatile("mma.sync.aligned.m16n8k16.row.col.f32.f16.f16.f32 " \
                 "{%0,%1,%2,%3}, {%4,%5,%6,%7}, {%8,%9}, {%0,%1,%2,%3};" \
                 : "+f"((c)[0]), "+f"((c)[1]), "+f"((c)[2]), "+f"((c)[3]) \
                 : "r"((a)[0]), "r"((a)[1]), "r"((a)[2]), "r"((a)[3]), \
                   "r"(b0), "r"(b1))

__device__ __forceinline__ void cpa16(uint32_t dst, const void* src, int sz) {
    asm volatile("cp.async.ca.shared.global [%0], [%1], 16, %2;"
                 :: "r"(dst), "l"(src), "r"(sz));
}
#define CP_COMMIT() asm volatile("cp.async.commit_group;" ::: "memory")
#define CP_WAIT1()  asm volatile("cp.async.wait_group 1;" ::: "memory")
#define CP_WAIT0()  asm volatile("cp.async.wait_group 0;" ::: "memory")

// smem stage layout: [AHI 16K][ALO 16K][B 16K] x 2 stages = 96 KB
#define STAGE_SZ 49152
#define OFF_ALO  16384
#define OFF_B    32768
#define SMEM_TOT (2 * STAGE_SZ)

// ---------------------------------------------------------------------------
// 1) zero g_pre / g_indeg + convert h, prev_h to fp16 hi/lo
// ---------------------------------------------------------------------------
__global__ void zero_conv_kernel(const float* __restrict__ h,
                                 const float* __restrict__ prev) {
    int i = blockIdx.x * blockDim.x + threadIdx.x;
    const int total4 = N_NODES * DIM / 4;
    float4 z = make_float4(0.f, 0.f, 0.f, 0.f);
    for (int idx = i; idx < total4; idx += gridDim.x * blockDim.x) {
        reinterpret_cast<float4*>(g_pre)[idx] = z;
        float4 hv = reinterpret_cast<const float4*>(h)[idx];
        float4 pv = reinterpret_cast<const float4*>(prev)[idx];
        __half2 hh0 = __floats2half2_rn(hv.x, hv.y);
        __half2 hh1 = __floats2half2_rn(hv.z, hv.w);
        __half2 hl0 = __floats2half2_rn(hv.x - __half2float(__low2half(hh0)),
                                        hv.y - __half2float(__high2half(hh0)));
        __half2 hl1 = __floats2half2_rn(hv.z - __half2float(__low2half(hh1)),
                                        hv.w - __half2float(__high2half(hh1)));
        __half2 ph0 = __floats2half2_rn(pv.x, pv.y);
        __half2 ph1 = __floats2half2_rn(pv.z, pv.w);
        __half2 pl0 = __floats2half2_rn(pv.x - __half2float(__low2half(ph0)),
                                        pv.y - __half2float(__high2half(ph0)));
        __half2 pl1 = __floats2half2_rn(pv.z - __half2float(__low2half(ph1)),
                                        pv.w - __half2float(__high2half(ph1)));
        reinterpret_cast<uint2*>(g_h_hi)[idx] =
            make_uint2(*reinterpret_cast<uint32_t*>(&hh0), *reinterpret_cast<uint32_t*>(&hh1));
        reinterpret_cast<uint2*>(g_h_lo)[idx] =
            make_uint2(*reinterpret_cast<uint32_t*>(&hl0), *reinterpret_cast<uint32_t*>(&hl1));
        reinterpret_cast<uint2*>(g_p_hi)[idx] =
            make_uint2(*reinterpret_cast<uint32_t*>(&ph0), *reinterpret_cast<uint32_t*>(&ph1));
        reinterpret_cast<uint2*>(g_p_lo)[idx] =
            make_uint2(*reinterpret_cast<uint32_t*>(&pl0), *reinterpret_cast<uint32_t*>(&pl1));
    }
    if (i < N_NODES) g_indeg[i] = 0;
}

// ---------------------------------------------------------------------------
// 1b) weight prep: transpose + fp16 convert
// ---------------------------------------------------------------------------
__global__ void prep_kernel(const float* __restrict__ Wn,
                            const float* __restrict__ L,
                            const float* __restrict__ Ws) {
    int idx = blockIdx.x * blockDim.x + threadIdx.x;
    if (idx < 256 * 512) {
        int n = idx >> 9;
        int k = idx & 511;
        float w = (k < 256) ? Wn[k * 256 + n] : L[(k - 256) * 256 + n];
        g_w1T[idx] = __float2half_rn(w);
    }
    if (idx < 256 * 256) {
        int n = idx >> 8;
        int k = idx & 255;
        g_w2T[idx] = __float2half_rn(Ws[k * 256 + n]);
    }
}

// ---------------------------------------------------------------------------
// 2) edge scatter: pre[dst] += h[src] + emb_rel[etype];  indeg[dst] += 1
// ---------------------------------------------------------------------------
__global__ void edge_kernel(const float* __restrict__ h,
                            const float* __restrict__ emb,
                            const int*   __restrict__ src,
                            const int*   __restrict__ dst,
                            const int*   __restrict__ etype) {
    long long tid = (long long)blockIdx.x * blockDim.x + threadIdx.x;
    int e = (int)(tid >> 5);
    int j = (int)(tid & 31);
    if (e >= N_EDGES) return;
    int s = src[e];
    int d = dst[e];
    int r = etype[e];
    if (j == 0) atomicAdd(&g_indeg[d], 1);

    const float4* hp = reinterpret_cast<const float4*>(h   + (size_t)s * DIM);
    const float4* ep = reinterpret_cast<const float4*>(emb + (size_t)r * DIM);
    #pragma unroll
    for (int q = 0; q < 2; q++) {
        int jj = j + q * 32;
        float4 hv = hp[jj];
        float4 ev = ep[jj];
        float4 v = make_float4(hv.x + ev.x, hv.y + ev.y, hv.z + ev.z, hv.w + ev.w);
        float* p = g_pre + (size_t)d * DIM + (size_t)jj * 4;
        asm volatile("red.global.add.v4.f32 [%0], {%1, %2, %3, %4};"
                     :: "l"(p), "f"(v.x), "f"(v.y), "f"(v.z), "f"(v.w) : "memory");
    }
}

// ---------------------------------------------------------------------------
// 2b) convert (pre * norm) -> fp16 hi/lo
// ---------------------------------------------------------------------------
__global__ void conv_pre_kernel(const float* __restrict__ norm) {
    int idx = blockIdx.x * blockDim.x + threadIdx.x;
    const int total4 = N_NODES * DIM / 4;
    if (idx >= total4) return;
    int row = idx >> 6;                    // 64 float4 per row
    float nm = __ldg(norm + row);
    float4 v = reinterpret_cast<const float4*>(g_pre)[idx];
    v.x *= nm; v.y *= nm; v.z *= nm; v.w *= nm;
    __half2 h0 = __floats2half2_rn(v.x, v.y);
    __half2 h1 = __floats2half2_rn(v.z, v.w);
    __half2 l0 = __floats2half2_rn(v.x - __half2float(__low2half(h0)),
                                   v.y - __half2float(__high2half(h0)));
    __half2 l1 = __floats2half2_rn(v.z - __half2float(__low2half(h1)),
                                   v.w - __half2float(__high2half(h1)));
    reinterpret_cast<uint2*>(g_pre_hi)[idx] =
        make_uint2(*reinterpret_cast<uint32_t*>(&h0), *reinterpret_cast<uint32_t*>(&h1));
    reinterpret_cast<uint2*>(g_pre_lo)[idx] =
        make_uint2(*reinterpret_cast<uint32_t*>(&l0), *reinterpret_cast<uint32_t*>(&l1));
}

// ---------------------------------------------------------------------------
// 3) pipelined fused GEMM (cp.async double-buffered, mma.sync fp16, fp32 acc)
//    chunks 0-3 : gate  D2 = prev @ Ws^T      (A-hi only, K=256)
//    chunks 4-11: main  D1 = [pre*norm|h] @ [Wn;L]^T  (A hi+lo, K=512)
//    gate epilogue (cc==3): sigmoid -> g_gate16
//    final epilogue: out = relu(gate*D1 + (1-gate)*prev)
// ---------------------------------------------------------------------------
__global__ __launch_bounds__(256, 2)
void fused_gemm_kernel(const float* __restrict__ prevh,
                       const float* __restrict__ bias,
                       float* __restrict__ out) {
    extern __shared__ char smem[];

    const int tid  = threadIdx.x;
    const int lane = tid & 31;
    const int wid  = tid >> 5;
    const int warpM = wid >> 2;          // 0..1
    const int warpN = wid & 3;           // 0..3
    const int row0  = blockIdx.x * 128;
    const int ncol0 = blockIdx.y * 128;

    // staging coords: thread t -> row t>>1, granules (t&1)*4 .. +3
    const int sRow = tid >> 1;
    const int sC16 = (tid & 1) * 4;

    // ldmatrix lane-address components
    const int aRow  = (lane & 7) + ((lane >> 3) & 1) * 8;
    const int aColB = ((lane >> 4) & 1) * 16;
    const int bRowO = ((lane >> 4) & 1) * 8 + (lane & 7);
    const int bColB = ((lane >> 3) & 1) * 16;

    const int rbase = row0 + warpM * 64;
    const int cbase = ncol0 + warpN * 32;

    // ---- stage issuer ----
    auto issue = [&](int cc, int buf) {
        char* base = smem + buf * STAGE_SZ;
        uint32_t sA = smem_u32(base);
        const __half *aH, *aL = nullptr, *bW;
        int kbA, kbB, KB;
        if (cc < 4) {
            aH = g_p_hi; kbA = cc * 64; bW = g_w2T; kbB = cc * 64; KB = 256;
        } else {
            int d = cc - 4;
            if (d < 4) { aH = g_pre_hi; aL = g_pre_lo; kbA = d * 64; }
            else       { aH = g_h_hi;   aL = g_h_lo;   kbA = (d - 4) * 64; }
            bW = g_w1T; kbB = d * 64; KB = 512;
        }
        int grow = row0 + sRow;
        int asz = (grow < N_NODES) ? 16 : 0;
        size_t aoff = (size_t)grow * DIM + kbA;
        size_t boff = (size_t)(ncol0 + sRow) * KB + kbB;
        #pragma unroll
        for (int i = 0; i < 4; i++) {
            int c16 = sC16 + i;
            uint32_t doff = SWZ((uint32_t)(sRow * 128 + c16 * 16));
            cpa16(sA + doff, aH + aoff + c16 * 8, asz);
            if (aL) cpa16(sA + OFF_ALO + doff, aL + aoff + c16 * 8, asz);
            cpa16(sA + OFF_B + doff, bW + boff + c16 * 8, 16);
        }
    };

    float acc[4][4][4];
    #pragma unroll
    for (int a = 0; a < 4; a++)
        #pragma unroll
        for (int b = 0; b < 4; b++)
            #pragma unroll
            for (int c = 0; c < 4; c++) acc[a][b][c] = 0.f;

    issue(0, 0);
    CP_COMMIT();

    for (int cc = 0; cc < 12; cc++) {
        int buf = cc & 1;
        if (cc + 1 < 12) {
            issue(cc + 1, (cc + 1) & 1);
            CP_COMMIT();
            CP_WAIT1();
        } else {
            CP_WAIT0();
        }
        __syncthreads();

        // ---- compute chunk cc from buffer buf ----
        {
            char* base = smem + buf * STAGE_SZ;
            uint32_t aHiB = smem_u32(base);
            uint32_t aLoB = aHiB + OFF_ALO;
            uint32_t bB   = aHiB + OFF_B;
            bool wantLo = (cc >= 4);
            #pragma unroll
            for (int k16 = 0; k16 < 4; k16++) {
                uint32_t bF[8];
                #pragma unroll
                for (int p = 0; p < 2; p++) {
                    int n = warpN * 32 + p * 16 + bRowO;
                    LDSM4(bF[4*p+0], bF[4*p+1], bF[4*p+2], bF[4*p+3],
                          bB + SWZ((uint32_t)(n * 128 + k16 * 32 + bColB)));
                }
                uint32_t aF[4][4];
                #pragma unroll
                for (int mt = 0; mt < 4; mt++) {
                    int r = warpM * 64 + mt * 16 + aRow;
                    LDSM4(aF[mt][0], aF[mt][1], aF[mt][2], aF[mt][3],
                          aHiB + SWZ((uint32_t)(r * 128 + k16 * 32 + aColB)));
                }
                #pragma unroll
                for (int mt = 0; mt < 4; mt++)
                    #pragma unroll
                    for (int nt = 0; nt < 4; nt++)
                        MMA16816(acc[mt][nt], aF[mt], bF[nt*2], bF[nt*2+1]);
                if (wantLo) {
                    #pragma unroll
                    for (int mt = 0; mt < 4; mt++) {
                        int r = warpM * 64 + mt * 16 + aRow;
                        LDSM4(aF[mt][0], aF[mt][1], aF[mt][2], aF[mt][3],
                              aLoB + SWZ((uint32_t)(r * 128 + k16 * 32 + aColB)));
                    }
                    #pragma unroll
                    for (int mt = 0; mt < 4; mt++)
                        #pragma unroll
                        for (int nt = 0; nt < 4; nt++)
                            MMA16816(acc[mt][nt], aF[mt], bF[nt*2], bF[nt*2+1]);
                }
            }
        }

        if (cc == 3) {
            // gate epilogue: sigmoid(D2 + bias) -> g_gate16 (fp16), reset acc
            #pragma unroll
            for (int mt = 0; mt < 4; mt++) {
                #pragma unroll
                for (int nt = 0; nt < 4; nt++) {
                    int gr = rbase + mt * 16 + (lane >> 2);
                    int gc = cbase + nt * 8 + (lane & 3) * 2;
                    float b0 = bias[gc], b1 = bias[gc + 1];
                    float g0 = 1.f / (1.f + __expf(-(acc[mt][nt][0] + b0)));
                    float g1 = 1.f / (1.f + __expf(-(acc[mt][nt][1] + b1)));
                    float g2 = 1.f / (1.f + __expf(-(acc[mt][nt][2] + b0)));
                    float g3 = 1.f / (1.f + __expf(-(acc[mt][nt][3] + b1)));
                    __half2 p01 = __floats2half2_rn(g0, g1);
                    __half2 p23 = __floats2half2_rn(g2, g3);
                    if (gr < N_NODES)
                        *reinterpret_cast<uint32_t*>(g_gate16 + (size_t)gr * DIM + gc) =
                            *reinterpret_cast<uint32_t*>(&p01);
                    if (gr + 8 < N_NODES)
                        *reinterpret_cast<uint32_t*>(g_gate16 + (size_t)(gr + 8) * DIM + gc) =
                            *reinterpret_cast<uint32_t*>(&p23);
                    acc[mt][nt][0] = 0.f; acc[mt][nt][1] = 0.f;
                    acc[mt][nt][2] = 0.f; acc[mt][nt][3] = 0.f;
                }
            }
        }
        __syncthreads();
    }

    // ---- final epilogue: out = relu(gate*D1 + (1-gate)*prev) ----
    #pragma unroll
    for (int mt = 0; mt < 4; mt++) {
        #pragma unroll
        for (int nt = 0; nt < 4; nt++) {
            int gr = rbase + mt * 16 + (lane >> 2);
            int gc = cbase + nt * 8 + (lane & 3) * 2;
            if (gr < N_NODES) {
                uint32_t u = *reinterpret_cast<const uint32_t*>(g_gate16 + (size_t)gr * DIM + gc);
                float2 g = __half22float2(*reinterpret_cast<__half2*>(&u));
                float2 pv = *reinterpret_cast<const float2*>(prevh + (size_t)gr * DIM + gc);
                float2 v;
                v.x = fmaxf(g.x * acc[mt][nt][0] + (1.f - g.x) * pv.x, 0.f);
                v.y = fmaxf(g.y * acc[mt][nt][1] + (1.f - g.y) * pv.y, 0.f);
                *reinterpret_cast<float2*>(out + (size_t)gr * DIM + gc) = v;
            }
            if (gr + 8 < N_NODES) {
                uint32_t u = *reinterpret_cast<const uint32_t*>(g_gate16 + (size_t)(gr + 8) * DIM + gc);
                float2 g = __half22float2(*reinterpret_cast<__half2*>(&u));
                float2 pv = *reinterpret_cast<const float2*>(prevh + (size_t)(gr + 8) * DIM + gc);
                float2 v;
                v.x = fmaxf(g.x * acc[mt][nt][2] + (1.f - g.x) * pv.x, 0.f);
                v.y = fmaxf(g.y * acc[mt][nt][3] + (1.f - g.y) * pv.y, 0.f);
                *reinterpret_cast<float2*>(out + (size_t)(gr + 8) * DIM + gc) = v;
            }
        }
    }
}

// ---------------------------------------------------------------------------
// 4) fixup for indeg==0 rows (~124): grid-stride scan of g_indeg.
//    out = relu(sig(prev@Ws + b) * (h@Wev) + (1-sig)*prev)   (exact fp32)
// ---------------------------------------------------------------------------
__global__ void fixup_kernel(const float* __restrict__ h,
                             const float* __restrict__ Wev,
                             const float* __restrict__ Ws,
                             const float* __restrict__ prevh,
                             const float* __restrict__ bias,
                             float* __restrict__ out) {
    __shared__ float hr[DIM];
    __shared__ float pr[DIM];
    int t = threadIdx.x;
    for (int n = blockIdx.x; n < N_NODES; n += gridDim.x) {
        if (g_indeg[n] != 0) continue;     // block-uniform
        hr[t] = h[(size_t)n * DIM + t];
        pr[t] = prevh[(size_t)n * DIM + t];
        __syncthreads();
        float accE = 0.f, accS = 0.f;
        #pragma unroll 8
        for (int k = 0; k < DIM; k++) {
            accE += hr[k] * Wev[(size_t)k * DIM + t];
            accS += pr[k] * Ws[(size_t)k * DIM + t];
        }
        float g = 1.f / (1.f + __expf(-(accS + bias[t])));
        out[(size_t)n * DIM + t] = fmaxf(g * accE + (1.f - g) * pr[t], 0.f);
        __syncthreads();
    }
}

// ---------------------------------------------------------------------------
extern "C" void kernel_launch(void* const* d_in, const int* in_sizes, int n_in,
                              void* d_out, int out_size) {
    const float* h       = (const float*)d_in[0];
    const float* prev_h  = (const float*)d_in[1];
    const float* emb_rel = (const float*)d_in[2];
    const float* norm    = (const float*)d_in[3];
    const float* w_n     = (const float*)d_in[4];
    const float* w_loop  = (const float*)d_in[5];
    const float* w_ev    = (const float*)d_in[6];
    const float* w_skip  = (const float*)d_in[7];
    const float* b_skip  = (const float*)d_in[8];
    const int*   src     = (const int*)d_in[9];
    const int*   dst     = (const int*)d_in[10];
    const int*   etype   = (const int*)d_in[11];
    float* out = (float*)d_out;

    cudaFuncSetAttribute(fused_gemm_kernel,
                         cudaFuncAttributeMaxDynamicSharedMemorySize, SMEM_TOT);

    zero_conv_kernel<<<2048, 256>>>(h, prev_h);                // 1
    prep_kernel<<<512, 256>>>(w_n, w_loop, w_skip);            // 2

    {
        long long threads = (long long)N_EDGES * 32;
        int blocks = (int)((threads + 255) / 256);
        edge_kernel<<<blocks, 256>>>(h, emb_rel, src, dst, etype);   // 3
    }

    {
        int total4 = N_NODES * DIM / 4;
        conv_pre_kernel<<<(total4 + 255) / 256, 256>>>(norm);  // 4
    }

    {
        dim3 grid((N_NODES + 127) / 128, 2);
        fused_gemm_kernel<<<grid, 256, SMEM_TOT>>>(prev_h, b_skip, out);  // 5
    }

    fixup_kernel<<<1024, DIM>>>(h, w_ev, w_skip, prev_h, b_skip, out);    // 6
}

// round 9
// speedup vs baseline: 1.0681x; 1.0681x over previous
#include <cuda_runtime.h>
#include <cuda_fp16.h>
#include <math.h>
#include <stdint.h>

#define N_NODES 50000
#define N_EDGES 300000
#define DIM 256
#define N_RELS 500

// ---------------------------------------------------------------------------
// Device-global scratch (never passed from host — R1 lesson)
// ---------------------------------------------------------------------------
__device__ float  g_pre[N_NODES * DIM];    // fp32 segment-sum target (atomics)
__device__ int    g_indeg[N_NODES];
__device__ __half g_h_hi [N_NODES * DIM];
__device__ __half g_h_lo [N_NODES * DIM];
__device__ __half g_p_hi [N_NODES * DIM];
__device__ __half g_p_lo [N_NODES * DIM];
__device__ __half g_pre_hi[N_NODES * DIM]; // (pre * norm) hi/lo
__device__ __half g_pre_lo[N_NODES * DIM];
__device__ __half g_gate16[N_NODES * DIM]; // sigmoid(prev@Ws+b), fp16
__device__ __half g_w1T[256 * 512];        // [Wn ; L]^T  (n-major rows, k contiguous)
__device__ __half g_w2T[256 * 256];        // Ws^T

// ---------------------------------------------------------------------------
// helpers
// ---------------------------------------------------------------------------
__device__ __forceinline__ uint32_t smem_u32(const void* p) {
    uint32_t a;
    asm("{ .reg .u64 t; cvta.to.shared.u64 t, %1; cvt.u32.u64 %0, t; }"
        : "=r"(a) : "l"(p));
    return a;
}
#define SWZ(o) ((o) ^ (((o) >> 3) & 0x70))

#define LDSM4(r0, r1, r2, r3, addr) \
    asm volatile("ldmatrix.sync.aligned.m8n8.x4.shared.b16 {%0,%1,%2,%3}, [%4];" \
                 : "=r"(r0), "=r"(r1), "=r"(r2), "=r"(r3) : "r"(addr))

#define MMA16816(c, a, b0, b1) \
    asm volatile("mma.sync.aligned.m16n8k16.row.col.f32.f16.f16.f32 " \
                 "{%0,%1,%2,%3}, {%4,%5,%6,%7}, {%8,%9}, {%0,%1,%2,%3};" \
                 : "+f"((c)[0]), "+f"((c)[1]), "+f"((c)[2]), "+f"((c)[3]) \
                 : "r"((a)[0]), "r"((a)[1]), "r"((a)[2]), "r"((a)[3]), \
                   "r"(b0), "r"(b1))

__device__ __forceinline__ void cpa16(uint32_t dst, const void* src, int sz) {
    asm volatile("cp.async.ca.shared.global [%0], [%1], 16, %2;"
                 :: "r"(dst), "l"(src), "r"(sz));
}
#define CP_COMMIT() asm volatile("cp.async.commit_group;" ::: "memory")
#define CP_WAIT1()  asm volatile("cp.async.wait_group 1;" ::: "memory")
#define CP_WAIT0()  asm volatile("cp.async.wait_group 0;" ::: "memory")

// smem stage layout: [AHI 16K][ALO 16K][B 32K] x 2 stages = 128 KB
#define OFF_ALO  16384
#define OFF_B    32768
#define STAGE_SZ 65536
#define SMEM_TOT (2 * STAGE_SZ)

// ---------------------------------------------------------------------------
// 1) zero g_pre / g_indeg + convert h, prev_h to fp16 hi/lo
// ---------------------------------------------------------------------------
__global__ void zero_conv_kernel(const float* __restrict__ h,
                                 const float* __restrict__ prev) {
    int i = blockIdx.x * blockDim.x + threadIdx.x;
    const int total4 = N_NODES * DIM / 4;
    float4 z = make_float4(0.f, 0.f, 0.f, 0.f);
    for (int idx = i; idx < total4; idx += gridDim.x * blockDim.x) {
        reinterpret_cast<float4*>(g_pre)[idx] = z;
        float4 hv = reinterpret_cast<const float4*>(h)[idx];
        float4 pv = reinterpret_cast<const float4*>(prev)[idx];
        __half2 hh0 = __floats2half2_rn(hv.x, hv.y);
        __half2 hh1 = __floats2half2_rn(hv.z, hv.w);
        __half2 hl0 = __floats2half2_rn(hv.x - __half2float(__low2half(hh0)),
                                        hv.y - __half2float(__high2half(hh0)));
        __half2 hl1 = __floats2half2_rn(hv.z - __half2float(__low2half(hh1)),
                                        hv.w - __half2float(__high2half(hh1)));
        __half2 ph0 = __floats2half2_rn(pv.x, pv.y);
        __half2 ph1 = __floats2half2_rn(pv.z, pv.w);
        __half2 pl0 = __floats2half2_rn(pv.x - __half2float(__low2half(ph0)),
                                        pv.y - __half2float(__high2half(ph0)));
        __half2 pl1 = __floats2half2_rn(pv.z - __half2float(__low2half(ph1)),
                                        pv.w - __half2float(__high2half(ph1)));
        reinterpret_cast<uint2*>(g_h_hi)[idx] =
            make_uint2(*reinterpret_cast<uint32_t*>(&hh0), *reinterpret_cast<uint32_t*>(&hh1));
        reinterpret_cast<uint2*>(g_h_lo)[idx] =
            make_uint2(*reinterpret_cast<uint32_t*>(&hl0), *reinterpret_cast<uint32_t*>(&hl1));
        reinterpret_cast<uint2*>(g_p_hi)[idx] =
            make_uint2(*reinterpret_cast<uint32_t*>(&ph0), *reinterpret_cast<uint32_t*>(&ph1));
        reinterpret_cast<uint2*>(g_p_lo)[idx] =
            make_uint2(*reinterpret_cast<uint32_t*>(&pl0), *reinterpret_cast<uint32_t*>(&pl1));
    }
    if (i < N_NODES) g_indeg[i] = 0;
}

// ---------------------------------------------------------------------------
// 1b/1c) weight prep: transpose + fp16 convert (split for launch-slot layout)
// ---------------------------------------------------------------------------
__global__ void prep_w1_kernel(const float* __restrict__ Wn,
                               const float* __restrict__ L) {
    int idx = blockIdx.x * blockDim.x + threadIdx.x;
    if (idx < 256 * 512) {
        int n = idx >> 9;
        int k = idx & 511;
        float w = (k < 256) ? Wn[k * 256 + n] : L[(k - 256) * 256 + n];
        g_w1T[idx] = __float2half_rn(w);
    }
}
__global__ void prep_w2_kernel(const float* __restrict__ Ws) {
    int idx = blockIdx.x * blockDim.x + threadIdx.x;
    if (idx < 256 * 256) {
        int n = idx >> 8;
        int k = idx & 255;
        g_w2T[idx] = __float2half_rn(Ws[k * 256 + n]);
    }
}

// ---------------------------------------------------------------------------
// 2) edge scatter: pre[dst] += h[src] + emb_rel[etype];  indeg[dst] += 1
//    (launch slot #4 -> profiled this round)
// ---------------------------------------------------------------------------
__global__ void edge_kernel(const float* __restrict__ h,
                            const float* __restrict__ emb,
                            const int*   __restrict__ src,
                            const int*   __restrict__ dst,
                            const int*   __restrict__ etype) {
    long long tid = (long long)blockIdx.x * blockDim.x + threadIdx.x;
    int e = (int)(tid >> 5);
    int j = (int)(tid & 31);
    if (e >= N_EDGES) return;
    int s = src[e];
    int d = dst[e];
    int r = etype[e];
    if (j == 0) atomicAdd(&g_indeg[d], 1);

    const float4* hp = reinterpret_cast<const float4*>(h   + (size_t)s * DIM);
    const float4* ep = reinterpret_cast<const float4*>(emb + (size_t)r * DIM);
    #pragma unroll
    for (int q = 0; q < 2; q++) {
        int jj = j + q * 32;
        float4 hv = hp[jj];
        float4 ev = ep[jj];
        float4 v = make_float4(hv.x + ev.x, hv.y + ev.y, hv.z + ev.z, hv.w + ev.w);
        float* p = g_pre + (size_t)d * DIM + (size_t)jj * 4;
        asm volatile("red.global.add.v4.f32 [%0], {%1, %2, %3, %4};"
                     :: "l"(p), "f"(v.x), "f"(v.y), "f"(v.z), "f"(v.w) : "memory");
    }
}

// ---------------------------------------------------------------------------
// 2b) convert (pre * norm) -> fp16 hi/lo
// ---------------------------------------------------------------------------
__global__ void conv_pre_kernel(const float* __restrict__ norm) {
    int idx = blockIdx.x * blockDim.x + threadIdx.x;
    const int total4 = N_NODES * DIM / 4;
    if (idx >= total4) return;
    int row = idx >> 6;
    float nm = __ldg(norm + row);
    float4 v = reinterpret_cast<const float4*>(g_pre)[idx];
    v.x *= nm; v.y *= nm; v.z *= nm; v.w *= nm;
    __half2 h0 = __floats2half2_rn(v.x, v.y);
    __half2 h1 = __floats2half2_rn(v.z, v.w);
    __half2 l0 = __floats2half2_rn(v.x - __half2float(__low2half(h0)),
                                   v.y - __half2float(__high2half(h0)));
    __half2 l1 = __floats2half2_rn(v.z - __half2float(__low2half(h1)),
                                   v.w - __half2float(__high2half(h1)));
    reinterpret_cast<uint2*>(g_pre_hi)[idx] =
        make_uint2(*reinterpret_cast<uint32_t*>(&h0), *reinterpret_cast<uint32_t*>(&h1));
    reinterpret_cast<uint2*>(g_pre_lo)[idx] =
        make_uint2(*reinterpret_cast<uint32_t*>(&l0), *reinterpret_cast<uint32_t*>(&l1));
}

// ---------------------------------------------------------------------------
// 3) pipelined fused GEMM — CTA tile 128 rows x 256 cols, 512 threads,
//    2-stage cp.async. A loaded ONCE per row-block (was twice).
//    chunks 0-3 : gate  D2 = prev @ Ws^T      (A-hi only, K=256)
//    chunks 4-11: main  D1 = [pre*norm|h] @ [Wn;L]^T  (A hi+lo, K=512)
//    16 warps: warpM = wid>>3 (2), warpN = wid&7 (8); warp tile 64x32.
// ---------------------------------------------------------------------------
__global__ __launch_bounds__(512, 1)
void fused_gemm_kernel(const float* __restrict__ prevh,
                       const float* __restrict__ bias,
                       float* __restrict__ out) {
    extern __shared__ char smem[];

    const int tid  = threadIdx.x;
    const int lane = tid & 31;
    const int wid  = tid >> 5;
    const int warpM = wid >> 3;          // 0..1
    const int warpN = wid & 7;           // 0..7
    const int row0  = blockIdx.x * 128;

    // staging coords
    const int aRowS = tid >> 2;          // 0..127 (A rows)
    const int aC16  = (tid & 3) * 2;     // granule base (2 granules)
    const int bRowS = tid >> 1;          // 0..255 (B n-rows)
    const int bC16  = (tid & 1) * 4;     // granule base (4 granules)

    // ldmatrix lane-address components
    const int aRow  = (lane & 7) + ((lane >> 3) & 1) * 8;
    const int aColB = ((lane >> 4) & 1) * 16;
    const int bRowO = ((lane >> 4) & 1) * 8 + (lane & 7);
    const int bColB = ((lane >> 3) & 1) * 16;

    const int rbase = row0 + warpM * 64;
    const int cbase = warpN * 32;

    auto issue = [&](int cc, int buf) {
        uint32_t sA = smem_u32(smem + buf * STAGE_SZ);
        const __half *aH, *aL = nullptr, *bW;
        int kbA, kbB, KB;
        if (cc < 4) {
            aH = g_p_hi; kbA = cc * 64; bW = g_w2T; kbB = cc * 64; KB = 256;
        } else {
            int d = cc - 4;
            if (d < 4) { aH = g_pre_hi; aL = g_pre_lo; kbA = d * 64; }
            else       { aH = g_h_hi;   aL = g_h_lo;   kbA = (d - 4) * 64; }
            bW = g_w1T; kbB = d * 64; KB = 512;
        }
        int grow = row0 + aRowS;
        int asz = (grow < N_NODES) ? 16 : 0;
        size_t aoff = (size_t)grow * DIM + kbA;
        #pragma unroll
        for (int i = 0; i < 2; i++) {
            int c16 = aC16 + i;
            uint32_t doff = SWZ((uint32_t)(aRowS * 128 + c16 * 16));
            cpa16(sA + doff, aH + aoff + c16 * 8, asz);
            if (aL) cpa16(sA + OFF_ALO + doff, aL + aoff + c16 * 8, asz);
        }
        size_t boff = (size_t)bRowS * KB + kbB;
        #pragma unroll
        for (int i = 0; i < 4; i++) {
            int c16 = bC16 + i;
            uint32_t doff = SWZ((uint32_t)(bRowS * 128 + c16 * 16));
            cpa16(sA + OFF_B + doff, bW + boff + c16 * 8, 16);
        }
    };

    float acc[4][4][4];
    #pragma unroll
    for (int a = 0; a < 4; a++)
        #pragma unroll
        for (int b = 0; b < 4; b++)
            #pragma unroll
            for (int c = 0; c < 4; c++) acc[a][b][c] = 0.f;

    issue(0, 0);
    CP_COMMIT();

    for (int cc = 0; cc < 12; cc++) {
        int buf = cc & 1;
        if (cc + 1 < 12) {
            issue(cc + 1, (cc + 1) & 1);
            CP_COMMIT();
            CP_WAIT1();
        } else {
            CP_WAIT0();
        }
        __syncthreads();

        {
            uint32_t aHiB = smem_u32(smem + buf * STAGE_SZ);
            uint32_t aLoB = aHiB + OFF_ALO;
            uint32_t bB   = aHiB + OFF_B;
            bool wantLo = (cc >= 4);
            #pragma unroll
            for (int k16 = 0; k16 < 4; k16++) {
                uint32_t bF[8];
                #pragma unroll
                for (int p = 0; p < 2; p++) {
                    int n = warpN * 32 + p * 16 + bRowO;
                    LDSM4(bF[4*p+0], bF[4*p+1], bF[4*p+2], bF[4*p+3],
                          bB + SWZ((uint32_t)(n * 128 + k16 * 32 + bColB)));
                }
                uint32_t aF[4][4];
                #pragma unroll
                for (int mt = 0; mt < 4; mt++) {
                    int r = warpM * 64 + mt * 16 + aRow;
                    LDSM4(aF[mt][0], aF[mt][1], aF[mt][2], aF[mt][3],
                          aHiB + SWZ((uint32_t)(r * 128 + k16 * 32 + aColB)));
                }
                #pragma unroll
                for (int mt = 0; mt < 4; mt++)
                    #pragma unroll
                    for (int nt = 0; nt < 4; nt++)
                        MMA16816(acc[mt][nt], aF[mt], bF[nt*2], bF[nt*2+1]);
                if (wantLo) {
                    #pragma unroll
                    for (int mt = 0; mt < 4; mt++) {
                        int r = warpM * 64 + mt * 16 + aRow;
                        LDSM4(aF[mt][0], aF[mt][1], aF[mt][2], aF[mt][3],
                              aLoB + SWZ((uint32_t)(r * 128 + k16 * 32 + aColB)));
                    }
                    #pragma unroll
                    for (int mt = 0; mt < 4; mt++)
                        #pragma unroll
                        for (int nt = 0; nt < 4; nt++)
                            MMA16816(acc[mt][nt], aF[mt], bF[nt*2], bF[nt*2+1]);
                }
            }
        }

        if (cc == 3) {
            // gate epilogue: sigmoid(D2 + bias) -> g_gate16, reset acc
            #pragma unroll
            for (int mt = 0; mt < 4; mt++) {
                #pragma unroll
                for (int nt = 0; nt < 4; nt++) {
                    int gr = rbase + mt * 16 + (lane >> 2);
                    int gc = cbase + nt * 8 + (lane & 3) * 2;
                    float b0 = bias[gc], b1 = bias[gc + 1];
                    float g0 = 1.f / (1.f + __expf(-(acc[mt][nt][0] + b0)));
                    float g1 = 1.f / (1.f + __expf(-(acc[mt][nt][1] + b1)));
                    float g2 = 1.f / (1.f + __expf(-(acc[mt][nt][2] + b0)));
                    float g3 = 1.f / (1.f + __expf(-(acc[mt][nt][3] + b1)));
                    __half2 p01 = __floats2half2_rn(g0, g1);
                    __half2 p23 = __floats2half2_rn(g2, g3);
                    if (gr < N_NODES)
                        *reinterpret_cast<uint32_t*>(g_gate16 + (size_t)gr * DIM + gc) =
                            *reinterpret_cast<uint32_t*>(&p01);
                    if (gr + 8 < N_NODES)
                        *reinterpret_cast<uint32_t*>(g_gate16 + (size_t)(gr + 8) * DIM + gc) =
                            *reinterpret_cast<uint32_t*>(&p23);
                    acc[mt][nt][0] = 0.f; acc[mt][nt][1] = 0.f;
                    acc[mt][nt][2] = 0.f; acc[mt][nt][3] = 0.f;
                }
            }
        }
        __syncthreads();
    }

    // final epilogue: out = relu(gate*D1 + (1-gate)*prev)
    #pragma unroll
    for (int mt = 0; mt < 4; mt++) {
        #pragma unroll
        for (int nt = 0; nt < 4; nt++) {
            int gr = rbase + mt * 16 + (lane >> 2);
            int gc = cbase + nt * 8 + (lane & 3) * 2;
            if (gr < N_NODES) {
                uint32_t u = *reinterpret_cast<const uint32_t*>(g_gate16 + (size_t)gr * DIM + gc);
                float2 g = __half22float2(*reinterpret_cast<__half2*>(&u));
                float2 pv = *reinterpret_cast<const float2*>(prevh + (size_t)gr * DIM + gc);
                float2 v;
                v.x = fmaxf(g.x * acc[mt][nt][0] + (1.f - g.x) * pv.x, 0.f);
                v.y = fmaxf(g.y * acc[mt][nt][1] + (1.f - g.y) * pv.y, 0.f);
                *reinterpret_cast<float2*>(out + (size_t)gr * DIM + gc) = v;
            }
            if (gr + 8 < N_NODES) {
                uint32_t u = *reinterpret_cast<const uint32_t*>(g_gate16 + (size_t)(gr + 8) * DIM + gc);
                float2 g = __half22float2(*reinterpret_cast<__half2*>(&u));
                float2 pv = *reinterpret_cast<const float2*>(prevh + (size_t)(gr + 8) * DIM + gc);
                float2 v;
                v.x = fmaxf(g.x * acc[mt][nt][2] + (1.f - g.x) * pv.x, 0.f);
                v.y = fmaxf(g.y * acc[mt][nt][3] + (1.f - g.y) * pv.y, 0.f);
                *reinterpret_cast<float2*>(out + (size_t)(gr + 8) * DIM + gc) = v;
            }
        }
    }
}

// ---------------------------------------------------------------------------
// 4) fixup for indeg==0 rows (~124): grid-stride scan of g_indeg.
// ---------------------------------------------------------------------------
__global__ void fixup_kernel(const float* __restrict__ h,
                             const float* __restrict__ Wev,
                             const float* __restrict__ Ws,
                             const float* __restrict__ prevh,
                             const float* __restrict__ bias,
                             float* __restrict__ out) {
    __shared__ float hr[DIM];
    __shared__ float pr[DIM];
    int t = threadIdx.x;
    for (int n = blockIdx.x; n < N_NODES; n += gridDim.x) {
        if (g_indeg[n] != 0) continue;
        hr[t] = h[(size_t)n * DIM + t];
        pr[t] = prevh[(size_t)n * DIM + t];
        __syncthreads();
        float accE = 0.f, accS = 0.f;
        #pragma unroll 8
        for (int k = 0; k < DIM; k++) {
            accE += hr[k] * Wev[(size_t)k * DIM + t];
            accS += pr[k] * Ws[(size_t)k * DIM + t];
        }
        float g = 1.f / (1.f + __expf(-(accS + bias[t])));
        out[(size_t)n * DIM + t] = fmaxf(g * accE + (1.f - g) * pr[t], 0.f);
        __syncthreads();
    }
}

// ---------------------------------------------------------------------------
extern "C" void kernel_launch(void* const* d_in, const int* in_sizes, int n_in,
                              void* d_out, int out_size) {
    const float* h       = (const float*)d_in[0];
    const float* prev_h  = (const float*)d_in[1];
    const float* emb_rel = (const float*)d_in[2];
    const float* norm    = (const float*)d_in[3];
    const float* w_n     = (const float*)d_in[4];
    const float* w_loop  = (const float*)d_in[5];
    const float* w_ev    = (const float*)d_in[6];
    const float* w_skip  = (const float*)d_in[7];
    const float* b_skip  = (const float*)d_in[8];
    const int*   src     = (const int*)d_in[9];
    const int*   dst     = (const int*)d_in[10];
    const int*   etype   = (const int*)d_in[11];
    float* out = (float*)d_out;

    cudaFuncSetAttribute(fused_gemm_kernel,
                         cudaFuncAttributeMaxDynamicSharedMemorySize, SMEM_TOT);

    zero_conv_kernel<<<2048, 256>>>(h, prev_h);                    // 1
    prep_w1_kernel<<<512, 256>>>(w_n, w_loop);                     // 2
    prep_w2_kernel<<<256, 256>>>(w_skip);                          // 3

    {
        long long threads = (long long)N_EDGES * 32;
        int blocks = (int)((threads + 255) / 256);
        edge_kernel<<<blocks, 256>>>(h, emb_rel, src, dst, etype); // 4 (profiled)
    }

    {
        int total4 = N_NODES * DIM / 4;
        conv_pre_kernel<<<(total4 + 255) / 256, 256>>>(norm);      // 5
    }

    {
        dim3 grid((N_NODES + 127) / 128);
        fused_gemm_kernel<<<grid, 512, SMEM_TOT>>>(prev_h, b_skip, out);  // 6
    }

    fixup_kernel<<<1024, DIM>>>(h, w_ev, w_skip, prev_h, b_skip, out);    // 7
}

// round 10
// speedup vs baseline: 1.2048x; 1.1280x over previous
#include <cuda_runtime.h>
#include <cuda_fp16.h>
#include <math.h>
#include <stdint.h>

#define N_NODES 50000
#define N_EDGES 300000
#define DIM 256
#define N_RELS 500

// ---------------------------------------------------------------------------
// Device-global scratch (never passed from host — R1 lesson)
// ---------------------------------------------------------------------------
__device__ float  g_pre[N_NODES * DIM];    // fp32 segment-sum target (atomics)
__device__ int    g_indeg[N_NODES];
__device__ __half g_h16  [N_NODES * DIM];  // h, fp16
__device__ __half g_p16  [N_NODES * DIM];  // prev_h, fp16
__device__ __half g_pre16[N_NODES * DIM];  // (pre * norm), fp16
__device__ __half g_gate16[N_NODES * DIM]; // sigmoid(prev@Ws+b), fp16
__device__ __half g_w1T[256 * 512];        // [Wn ; L]^T  (n rows, k contiguous)
__device__ __half g_w2T[256 * 256];        // Ws^T

// ---------------------------------------------------------------------------
// helpers
// ---------------------------------------------------------------------------
__device__ __forceinline__ uint32_t smem_u32(const void* p) {
    uint32_t a;
    asm("{ .reg .u64 t; cvta.to.shared.u64 t, %1; cvt.u32.u64 %0, t; }"
        : "=r"(a) : "l"(p));
    return a;
}
#define SWZ(o) ((o) ^ (((o) >> 3) & 0x70))

#define LDSM4(r0, r1, r2, r3, addr) \
    asm volatile("ldmatrix.sync.aligned.m8n8.x4.shared.b16 {%0,%1,%2,%3}, [%4];" \
                 : "=r"(r0), "=r"(r1), "=r"(r2), "=r"(r3) : "r"(addr))

#define MMA16816(c, a, b0, b1) \
    asm volatile("mma.sync.aligned.m16n8k16.row.col.f32.f16.f16.f32 " \
                 "{%0,%1,%2,%3}, {%4,%5,%6,%7}, {%8,%9}, {%0,%1,%2,%3};" \
                 : "+f"((c)[0]), "+f"((c)[1]), "+f"((c)[2]), "+f"((c)[3]) \
                 : "r"((a)[0]), "r"((a)[1]), "r"((a)[2]), "r"((a)[3]), \
                   "r"(b0), "r"(b1))

__device__ __forceinline__ void cpa16(uint32_t dst, const void* src, int sz) {
    asm volatile("cp.async.ca.shared.global [%0], [%1], 16, %2;"
                 :: "r"(dst), "l"(src), "r"(sz));
}
#define CP_COMMIT() asm volatile("cp.async.commit_group;" ::: "memory")
#define CP_WAIT2()  asm volatile("cp.async.wait_group 2;" ::: "memory")
#define CP_WAIT1()  asm volatile("cp.async.wait_group 1;" ::: "memory")
#define CP_WAIT0()  asm volatile("cp.async.wait_group 0;" ::: "memory")

// smem stage layout: [A 16K][B 32K] x 3 stages = 144 KB (1 CTA/SM)
#define OFF_B    16384
#define STAGE_SZ 49152
#define SMEM_TOT (3 * STAGE_SZ)

// ---------------------------------------------------------------------------
// 1) merged: zero g_pre/g_indeg, convert h & prev_h -> fp16, prep weights
// ---------------------------------------------------------------------------
__global__ void zero_prep_kernel(const float* __restrict__ h,
                                 const float* __restrict__ prev,
                                 const float* __restrict__ Wn,
                                 const float* __restrict__ L,
                                 const float* __restrict__ Ws) {
    int i = blockIdx.x * blockDim.x + threadIdx.x;
    const int total4 = N_NODES * DIM / 4;
    float4 z = make_float4(0.f, 0.f, 0.f, 0.f);
    for (int idx = i; idx < total4; idx += gridDim.x * blockDim.x) {
        reinterpret_cast<float4*>(g_pre)[idx] = z;
        float4 hv = reinterpret_cast<const float4*>(h)[idx];
        float4 pv = reinterpret_cast<const float4*>(prev)[idx];
        __half2 hh0 = __floats2half2_rn(hv.x, hv.y);
        __half2 hh1 = __floats2half2_rn(hv.z, hv.w);
        __half2 ph0 = __floats2half2_rn(pv.x, pv.y);
        __half2 ph1 = __floats2half2_rn(pv.z, pv.w);
        reinterpret_cast<uint2*>(g_h16)[idx] =
            make_uint2(*reinterpret_cast<uint32_t*>(&hh0), *reinterpret_cast<uint32_t*>(&hh1));
        reinterpret_cast<uint2*>(g_p16)[idx] =
            make_uint2(*reinterpret_cast<uint32_t*>(&ph0), *reinterpret_cast<uint32_t*>(&ph1));
    }
    if (i < N_NODES) g_indeg[i] = 0;
    if (i < 256 * 512) {
        int n = i >> 9;
        int k = i & 511;
        float w = (k < 256) ? Wn[k * 256 + n] : L[(k - 256) * 256 + n];
        g_w1T[i] = __float2half_rn(w);
    }
    if (i < 256 * 256) {
        int n = i >> 8;
        int k = i & 255;
        g_w2T[i] = __float2half_rn(Ws[k * 256 + n]);
    }
}

// ---------------------------------------------------------------------------
// 2) edge scatter: pre[dst] += h[src] + emb_rel[etype];  indeg[dst] += 1
// ---------------------------------------------------------------------------
__global__ void edge_kernel(const float* __restrict__ h,
                            const float* __restrict__ emb,
                            const int*   __restrict__ src,
                            const int*   __restrict__ dst,
                            const int*   __restrict__ etype) {
    long long tid = (long long)blockIdx.x * blockDim.x + threadIdx.x;
    int e = (int)(tid >> 5);
    int j = (int)(tid & 31);
    if (e >= N_EDGES) return;
    int s = src[e];
    int d = dst[e];
    int r = etype[e];
    if (j == 0) atomicAdd(&g_indeg[d], 1);

    const float4* hp = reinterpret_cast<const float4*>(h   + (size_t)s * DIM);
    const float4* ep = reinterpret_cast<const float4*>(emb + (size_t)r * DIM);
    #pragma unroll
    for (int q = 0; q < 2; q++) {
        int jj = j + q * 32;
        float4 hv = hp[jj];
        float4 ev = ep[jj];
        float4 v = make_float4(hv.x + ev.x, hv.y + ev.y, hv.z + ev.z, hv.w + ev.w);
        float* p = g_pre + (size_t)d * DIM + (size_t)jj * 4;
        asm volatile("red.global.add.v4.f32 [%0], {%1, %2, %3, %4};"
                     :: "l"(p), "f"(v.x), "f"(v.y), "f"(v.z), "f"(v.w) : "memory");
    }
}

// ---------------------------------------------------------------------------
// 2b) convert (pre * norm) -> fp16
// ---------------------------------------------------------------------------
__global__ void conv_pre_kernel(const float* __restrict__ norm) {
    int idx = blockIdx.x * blockDim.x + threadIdx.x;
    const int total4 = N_NODES * DIM / 4;
    if (idx >= total4) return;
    int row = idx >> 6;
    float nm = __ldg(norm + row);
    float4 v = reinterpret_cast<const float4*>(g_pre)[idx];
    v.x *= nm; v.y *= nm; v.z *= nm; v.w *= nm;
    __half2 h0 = __floats2half2_rn(v.x, v.y);
    __half2 h1 = __floats2half2_rn(v.z, v.w);
    reinterpret_cast<uint2*>(g_pre16)[idx] =
        make_uint2(*reinterpret_cast<uint32_t*>(&h0), *reinterpret_cast<uint32_t*>(&h1));
}

// ---------------------------------------------------------------------------
// 3) pipelined fused GEMM — CTA tile 128 rows x 256 cols, 512 threads,
//    3-stage cp.async, single fp16 product per chunk.
//    chunks 0-3 : gate  D2 = prev @ Ws^T            (K=256)
//    chunks 4-11: main  D1 = [pre*norm|h] @ [Wn;L]^T (K=512)
//    16 warps: warpM = wid>>3 (2), warpN = wid&7 (8); warp tile 64x32.
// ---------------------------------------------------------------------------
__global__ __launch_bounds__(512, 1)
void fused_gemm_kernel(const float* __restrict__ prevh,
                       const float* __restrict__ bias,
                       float* __restrict__ out) {
    extern __shared__ char smem[];

    const int tid  = threadIdx.x;
    const int lane = tid & 31;
    const int wid  = tid >> 5;
    const int warpM = wid >> 3;          // 0..1
    const int warpN = wid & 7;           // 0..7
    const int row0  = blockIdx.x * 128;

    // staging coords
    const int aRowS = tid >> 2;          // 0..127 (A rows), 2 granules each
    const int aC16  = (tid & 3) * 2;
    const int bRowS = tid >> 1;          // 0..255 (B n-rows), 4 granules each
    const int bC16  = (tid & 1) * 4;

    // ldmatrix lane-address components
    const int aRow  = (lane & 7) + ((lane >> 3) & 1) * 8;
    const int aColB = ((lane >> 4) & 1) * 16;
    const int bRowO = ((lane >> 4) & 1) * 8 + (lane & 7);
    const int bColB = ((lane >> 3) & 1) * 16;

    const int rbase = row0 + warpM * 64;
    const int cbase = warpN * 32;

    auto issue = [&](int cc, int buf) {
        uint32_t sA = smem_u32(smem + buf * STAGE_SZ);
        const __half *aS, *bW;
        int kbA, kbB, KB;
        if (cc < 4) {
            aS = g_p16; kbA = cc * 64; bW = g_w2T; kbB = cc * 64; KB = 256;
        } else {
            int d = cc - 4;
            aS = (d < 4) ? g_pre16 : g_h16;
            kbA = (d & 3) * 64;
            bW = g_w1T; kbB = d * 64; KB = 512;
        }
        int grow = row0 + aRowS;
        int asz = (grow < N_NODES) ? 16 : 0;
        size_t aoff = (size_t)grow * DIM + kbA;
        #pragma unroll
        for (int i = 0; i < 2; i++) {
            int c16 = aC16 + i;
            uint32_t doff = SWZ((uint32_t)(aRowS * 128 + c16 * 16));
            cpa16(sA + doff, aS + aoff + c16 * 8, asz);
        }
        size_t boff = (size_t)bRowS * KB + kbB;
        #pragma unroll
        for (int i = 0; i < 4; i++) {
            int c16 = bC16 + i;
            uint32_t doff = SWZ((uint32_t)(bRowS * 128 + c16 * 16));
            cpa16(sA + OFF_B + doff, bW + boff + c16 * 8, 16);
        }
    };

    float acc[4][4][4];
    #pragma unroll
    for (int a = 0; a < 4; a++)
        #pragma unroll
        for (int b = 0; b < 4; b++)
            #pragma unroll
            for (int c = 0; c < 4; c++) acc[a][b][c] = 0.f;

    issue(0, 0); CP_COMMIT();
    issue(1, 1); CP_COMMIT();

    for (int cc = 0; cc < 12; cc++) {
        int buf = cc % 3;
        if (cc + 2 < 12) {
            issue(cc + 2, (cc + 2) % 3);
            CP_COMMIT();
            CP_WAIT2();
        } else if (cc + 1 < 12) {
            CP_WAIT1();
        } else {
            CP_WAIT0();
        }
        __syncthreads();

        {
            uint32_t aB = smem_u32(smem + buf * STAGE_SZ);
            uint32_t bB = aB + OFF_B;
            #pragma unroll
            for (int k16 = 0; k16 < 4; k16++) {
                uint32_t bF[8];
                #pragma unroll
                for (int p = 0; p < 2; p++) {
                    int n = warpN * 32 + p * 16 + bRowO;
                    LDSM4(bF[4*p+0], bF[4*p+1], bF[4*p+2], bF[4*p+3],
                          bB + SWZ((uint32_t)(n * 128 + k16 * 32 + bColB)));
                }
                uint32_t aF[4][4];
                #pragma unroll
                for (int mt = 0; mt < 4; mt++) {
                    int r = warpM * 64 + mt * 16 + aRow;
                    LDSM4(aF[mt][0], aF[mt][1], aF[mt][2], aF[mt][3],
                          aB + SWZ((uint32_t)(r * 128 + k16 * 32 + aColB)));
                }
                #pragma unroll
                for (int mt = 0; mt < 4; mt++)
                    #pragma unroll
                    for (int nt = 0; nt < 4; nt++)
                        MMA16816(acc[mt][nt], aF[mt], bF[nt*2], bF[nt*2+1]);
            }
        }

        if (cc == 3) {
            // gate epilogue: sigmoid(D2 + bias) -> g_gate16, reset acc
            #pragma unroll
            for (int mt = 0; mt < 4; mt++) {
                #pragma unroll
                for (int nt = 0; nt < 4; nt++) {
                    int gr = rbase + mt * 16 + (lane >> 2);
                    int gc = cbase + nt * 8 + (lane & 3) * 2;
                    float b0 = bias[gc], b1 = bias[gc + 1];
                    float g0 = 1.f / (1.f + __expf(-(acc[mt][nt][0] + b0)));
                    float g1 = 1.f / (1.f + __expf(-(acc[mt][nt][1] + b1)));
                    float g2 = 1.f / (1.f + __expf(-(acc[mt][nt][2] + b0)));
                    float g3 = 1.f / (1.f + __expf(-(acc[mt][nt][3] + b1)));
                    __half2 p01 = __floats2half2_rn(g0, g1);
                    __half2 p23 = __floats2half2_rn(g2, g3);
                    if (gr < N_NODES)
                        *reinterpret_cast<uint32_t*>(g_gate16 + (size_t)gr * DIM + gc) =
                            *reinterpret_cast<uint32_t*>(&p01);
                    if (gr + 8 < N_NODES)
                        *reinterpret_cast<uint32_t*>(g_gate16 + (size_t)(gr + 8) * DIM + gc) =
                            *reinterpret_cast<uint32_t*>(&p23);
                    acc[mt][nt][0] = 0.f; acc[mt][nt][1] = 0.f;
                    acc[mt][nt][2] = 0.f; acc[mt][nt][3] = 0.f;
                }
            }
        }
        __syncthreads();
    }

    // final epilogue: out = relu(gate*D1 + (1-gate)*prev)
    #pragma unroll
    for (int mt = 0; mt < 4; mt++) {
        #pragma unroll
        for (int nt = 0; nt < 4; nt++) {
            int gr = rbase + mt * 16 + (lane >> 2);
            int gc = cbase + nt * 8 + (lane & 3) * 2;
            if (gr < N_NODES) {
                uint32_t u = *reinterpret_cast<const uint32_t*>(g_gate16 + (size_t)gr * DIM + gc);
                float2 g = __half22float2(*reinterpret_cast<__half2*>(&u));
                float2 pv = *reinterpret_cast<const float2*>(prevh + (size_t)gr * DIM + gc);
                float2 v;
                v.x = fmaxf(g.x * acc[mt][nt][0] + (1.f - g.x) * pv.x, 0.f);
                v.y = fmaxf(g.y * acc[mt][nt][1] + (1.f - g.y) * pv.y, 0.f);
                *reinterpret_cast<float2*>(out + (size_t)gr * DIM + gc) = v;
            }
            if (gr + 8 < N_NODES) {
                uint32_t u = *reinterpret_cast<const uint32_t*>(g_gate16 + (size_t)(gr + 8) * DIM + gc);
                float2 g = __half22float2(*reinterpret_cast<__half2*>(&u));
                float2 pv = *reinterpret_cast<const float2*>(prevh + (size_t)(gr + 8) * DIM + gc);
                float2 v;
                v.x = fmaxf(g.x * acc[mt][nt][2] + (1.f - g.x) * pv.x, 0.f);
                v.y = fmaxf(g.y * acc[mt][nt][3] + (1.f - g.y) * pv.y, 0.f);
                *reinterpret_cast<float2*>(out + (size_t)(gr + 8) * DIM + gc) = v;
            }
        }
    }
}

// ---------------------------------------------------------------------------
// 4) fixup for indeg==0 rows (~124): grid-stride scan of g_indeg.
//    out = relu(sig(prev@Ws + b) * (h@Wev) + (1-sig)*prev)   (exact fp32)
// ---------------------------------------------------------------------------
__global__ void fixup_kernel(const float* __restrict__ h,
                             const float* __restrict__ Wev,
                             const float* __restrict__ Ws,
                             const float* __restrict__ prevh,
                             const float* __restrict__ bias,
                             float* __restrict__ out) {
    __shared__ float hr[DIM];
    __shared__ float pr[DIM];
    int t = threadIdx.x;
    for (int n = blockIdx.x; n < N_NODES; n += gridDim.x) {
        if (g_indeg[n] != 0) continue;
        hr[t] = h[(size_t)n * DIM + t];
        pr[t] = prevh[(size_t)n * DIM + t];
        __syncthreads();
        float accE = 0.f, accS = 0.f;
        #pragma unroll 8
        for (int k = 0; k < DIM; k++) {
            accE += hr[k] * Wev[(size_t)k * DIM + t];
            accS += pr[k] * Ws[(size_t)k * DIM + t];
        }
        float g = 1.f / (1.f + __expf(-(accS + bias[t])));
        out[(size_t)n * DIM + t] = fmaxf(g * accE + (1.f - g) * pr[t], 0.f);
        __syncthreads();
    }
}

// ---------------------------------------------------------------------------
extern "C" void kernel_launch(void* const* d_in, const int* in_sizes, int n_in,
                              void* d_out, int out_size) {
    const float* h       = (const float*)d_in[0];
    const float* prev_h  = (const float*)d_in[1];
    const float* emb_rel = (const float*)d_in[2];
    const float* norm    = (const float*)d_in[3];
    const float* w_n     = (const float*)d_in[4];
    const float* w_loop  = (const float*)d_in[5];
    const float* w_ev    = (const float*)d_in[6];
    const float* w_skip  = (const float*)d_in[7];
    const float* b_skip  = (const float*)d_in[8];
    const int*   src     = (const int*)d_in[9];
    const int*   dst     = (const int*)d_in[10];
    const int*   etype   = (const int*)d_in[11];
    float* out = (float*)d_out;

    cudaFuncSetAttribute(fused_gemm_kernel,
                         cudaFuncAttributeMaxDynamicSharedMemorySize, SMEM_TOT);

    zero_prep_kernel<<<2048, 256>>>(h, prev_h, w_n, w_loop, w_skip);   // 1

    {
        long long threads = (long long)N_EDGES * 32;
        int blocks = (int)((threads + 255) / 256);
        edge_kernel<<<blocks, 256>>>(h, emb_rel, src, dst, etype);     // 2
    }

    {
        int total4 = N_NODES * DIM / 4;
        conv_pre_kernel<<<(total4 + 255) / 256, 256>>>(norm);          // 3
    }

    {
        dim3 grid((N_NODES + 127) / 128);
        fused_gemm_kernel<<<grid, 512, SMEM_TOT>>>(prev_h, b_skip, out);  // 4 (profiled)
    }

    fixup_kernel<<<1024, DIM>>>(h, w_ev, w_skip, prev_h, b_skip, out);    // 5
}

// round 11
// speedup vs baseline: 1.2954x; 1.0752x over previous
#include <cuda_runtime.h>
#include <cuda_fp16.h>
#include <math.h>
#include <stdint.h>

#define N_NODES 50000
#define N_EDGES 300000
#define DIM 256
#define N_RELS 500

// ---------------------------------------------------------------------------
// Device-global scratch (never passed from host — R1 lesson)
// ---------------------------------------------------------------------------
__device__ float  g_pre[N_NODES * DIM];    // fp32 segment-sum target (atomics)
__device__ int    g_indeg[N_NODES];
__device__ int    g_list[N_NODES];
__device__ int    g_nfix;
__device__ __half g_h16  [N_NODES * DIM];  // h, fp16
__device__ __half g_p16  [N_NODES * DIM];  // prev_h, fp16
__device__ __half g_pre16[N_NODES * DIM];  // (pre * norm), fp16
__device__ __half g_w1T[256 * 512];        // [Wn ; L]^T  (n rows, k contiguous)
__device__ __half g_w2T[256 * 256];        // Ws^T

// ---------------------------------------------------------------------------
// helpers
// ---------------------------------------------------------------------------
__device__ __forceinline__ uint32_t smem_u32(const void* p) {
    uint32_t a;
    asm("{ .reg .u64 t; cvta.to.shared.u64 t, %1; cvt.u32.u64 %0, t; }"
        : "=r"(a) : "l"(p));
    return a;
}
#define SWZ(o) ((o) ^ (((o) >> 3) & 0x70))

#define LDSM4(r0, r1, r2, r3, addr) \
    asm volatile("ldmatrix.sync.aligned.m8n8.x4.shared.b16 {%0,%1,%2,%3}, [%4];" \
                 : "=r"(r0), "=r"(r1), "=r"(r2), "=r"(r3) : "r"(addr))

#define MMA16816(c, a, b0, b1) \
    asm volatile("mma.sync.aligned.m16n8k16.row.col.f32.f16.f16.f32 " \
                 "{%0,%1,%2,%3}, {%4,%5,%6,%7}, {%8,%9}, {%0,%1,%2,%3};" \
                 : "+f"((c)[0]), "+f"((c)[1]), "+f"((c)[2]), "+f"((c)[3]) \
                 : "r"((a)[0]), "r"((a)[1]), "r"((a)[2]), "r"((a)[3]), \
                   "r"(b0), "r"(b1))

__device__ __forceinline__ void cpa16(uint32_t dst, const void* src, int sz) {
    asm volatile("cp.async.ca.shared.global [%0], [%1], 16, %2;"
                 :: "r"(dst), "l"(src), "r"(sz));
}
#define CP_COMMIT() asm volatile("cp.async.commit_group;" ::: "memory")
#define CP_WAIT2()  asm volatile("cp.async.wait_group 2;" ::: "memory")
#define CP_WAIT1()  asm volatile("cp.async.wait_group 1;" ::: "memory")
#define CP_WAIT0()  asm volatile("cp.async.wait_group 0;" ::: "memory")

// smem: [A 16K][B 32K] x 3 stages = 144 KB, then gate store 64 KB = 208 KB
#define OFF_B    16384
#define STAGE_SZ 49152
#define OFF_GS   (3 * STAGE_SZ)
#define SMEM_TOT (3 * STAGE_SZ + 65536)

// ---------------------------------------------------------------------------
// 1) merged: zero g_pre/g_indeg/g_nfix, convert h & prev_h -> fp16, prep W
// ---------------------------------------------------------------------------
__global__ void zero_prep_kernel(const float* __restrict__ h,
                                 const float* __restrict__ prev,
                                 const float* __restrict__ Wn,
                                 const float* __restrict__ L,
                                 const float* __restrict__ Ws) {
    int i = blockIdx.x * blockDim.x + threadIdx.x;
    const int total4 = N_NODES * DIM / 4;
    float4 z = make_float4(0.f, 0.f, 0.f, 0.f);
    for (int idx = i; idx < total4; idx += gridDim.x * blockDim.x) {
        reinterpret_cast<float4*>(g_pre)[idx] = z;
        float4 hv = reinterpret_cast<const float4*>(h)[idx];
        float4 pv = reinterpret_cast<const float4*>(prev)[idx];
        __half2 hh0 = __floats2half2_rn(hv.x, hv.y);
        __half2 hh1 = __floats2half2_rn(hv.z, hv.w);
        __half2 ph0 = __floats2half2_rn(pv.x, pv.y);
        __half2 ph1 = __floats2half2_rn(pv.z, pv.w);
        reinterpret_cast<uint2*>(g_h16)[idx] =
            make_uint2(*reinterpret_cast<uint32_t*>(&hh0), *reinterpret_cast<uint32_t*>(&hh1));
        reinterpret_cast<uint2*>(g_p16)[idx] =
            make_uint2(*reinterpret_cast<uint32_t*>(&ph0), *reinterpret_cast<uint32_t*>(&ph1));
    }
    if (i < N_NODES) g_indeg[i] = 0;
    if (i == 0) g_nfix = 0;
    if (i < 256 * 512) {
        int n = i >> 9;
        int k = i & 511;
        float w = (k < 256) ? Wn[k * 256 + n] : L[(k - 256) * 256 + n];
        g_w1T[i] = __float2half_rn(w);
    }
    if (i < 256 * 256) {
        int n = i >> 8;
        int k = i & 255;
        g_w2T[i] = __float2half_rn(Ws[k * 256 + n]);
    }
}

// ---------------------------------------------------------------------------
// 2) edge scatter: pre[dst] += h[src] + emb_rel[etype];  indeg[dst] += 1
// ---------------------------------------------------------------------------
__global__ void edge_kernel(const float* __restrict__ h,
                            const float* __restrict__ emb,
                            const int*   __restrict__ src,
                            const int*   __restrict__ dst,
                            const int*   __restrict__ etype) {
    long long tid = (long long)blockIdx.x * blockDim.x + threadIdx.x;
    int e = (int)(tid >> 5);
    int j = (int)(tid & 31);
    if (e >= N_EDGES) return;
    int s = src[e];
    int d = dst[e];
    int r = etype[e];
    if (j == 0) atomicAdd(&g_indeg[d], 1);

    const float4* hp = reinterpret_cast<const float4*>(h   + (size_t)s * DIM);
    const float4* ep = reinterpret_cast<const float4*>(emb + (size_t)r * DIM);
    #pragma unroll
    for (int q = 0; q < 2; q++) {
        int jj = j + q * 32;
        float4 hv = hp[jj];
        float4 ev = ep[jj];
        float4 v = make_float4(hv.x + ev.x, hv.y + ev.y, hv.z + ev.z, hv.w + ev.w);
        float* p = g_pre + (size_t)d * DIM + (size_t)jj * 4;
        asm volatile("red.global.add.v4.f32 [%0], {%1, %2, %3, %4};"
                     :: "l"(p), "f"(v.x), "f"(v.y), "f"(v.z), "f"(v.w) : "memory");
    }
}

// ---------------------------------------------------------------------------
// 2b) convert (pre * norm) -> fp16 + build compact indeg==0 list
// ---------------------------------------------------------------------------
__global__ void conv_pre_kernel(const float* __restrict__ norm) {
    int idx = blockIdx.x * blockDim.x + threadIdx.x;
    const int total4 = N_NODES * DIM / 4;
    if (idx >= total4) return;
    int row = idx >> 6;
    if ((idx & 63) == 0 && g_indeg[row] == 0) {
        int slot = atomicAdd(&g_nfix, 1);
        g_list[slot] = row;
    }
    float nm = __ldg(norm + row);
    float4 v = reinterpret_cast<const float4*>(g_pre)[idx];
    v.x *= nm; v.y *= nm; v.z *= nm; v.w *= nm;
    __half2 h0 = __floats2half2_rn(v.x, v.y);
    __half2 h1 = __floats2half2_rn(v.z, v.w);
    reinterpret_cast<uint2*>(g_pre16)[idx] =
        make_uint2(*reinterpret_cast<uint32_t*>(&h0), *reinterpret_cast<uint32_t*>(&h1));
}

// ---------------------------------------------------------------------------
// 3) pipelined fused GEMM — CTA tile 128 rows x 256 cols, 512 threads,
//    3-stage cp.async; gate tile kept in SMEM (no DRAM round-trip).
//    chunks 0-3 : gate  D2 = prev @ Ws^T            (K=256)
//    chunks 4-11: main  D1 = [pre*norm|h] @ [Wn;L]^T (K=512)
// ---------------------------------------------------------------------------
__global__ __launch_bounds__(512, 1)
void fused_gemm_kernel(const float* __restrict__ prevh,
                       const float* __restrict__ bias,
                       float* __restrict__ out) {
    extern __shared__ char smem[];
    uint32_t* Gs = reinterpret_cast<uint32_t*>(smem + OFF_GS);  // [32][512]

    const int tid  = threadIdx.x;
    const int lane = tid & 31;
    const int wid  = tid >> 5;
    const int warpM = wid >> 3;          // 0..1
    const int warpN = wid & 7;           // 0..7
    const int row0  = blockIdx.x * 128;

    // staging coords
    const int aRowS = tid >> 2;          // 0..127 (A rows), 2 granules each
    const int aC16  = (tid & 3) * 2;
    const int bRowS = tid >> 1;          // 0..255 (B n-rows), 4 granules each
    const int bC16  = (tid & 1) * 4;

    // ldmatrix lane-address components
    const int aRow  = (lane & 7) + ((lane >> 3) & 1) * 8;
    const int aColB = ((lane >> 4) & 1) * 16;
    const int bRowO = ((lane >> 4) & 1) * 8 + (lane & 7);
    const int bColB = ((lane >> 3) & 1) * 16;

    const int rbase = row0 + warpM * 64;
    const int cbase = warpN * 32;

    auto issue = [&](int cc, int buf) {
        uint32_t sA = smem_u32(smem + buf * STAGE_SZ);
        const __half *aS, *bW;
        int kbA, kbB, KB;
        if (cc < 4) {
            aS = g_p16; kbA = cc * 64; bW = g_w2T; kbB = cc * 64; KB = 256;
        } else {
            int d = cc - 4;
            aS = (d < 4) ? g_pre16 : g_h16;
            kbA = (d & 3) * 64;
            bW = g_w1T; kbB = d * 64; KB = 512;
        }
        int grow = row0 + aRowS;
        int asz = (grow < N_NODES) ? 16 : 0;
        size_t aoff = (size_t)grow * DIM + kbA;
        #pragma unroll
        for (int i = 0; i < 2; i++) {
            int c16 = aC16 + i;
            uint32_t doff = SWZ((uint32_t)(aRowS * 128 + c16 * 16));
            cpa16(sA + doff, aS + aoff + c16 * 8, asz);
        }
        size_t boff = (size_t)bRowS * KB + kbB;
        #pragma unroll
        for (int i = 0; i < 4; i++) {
            int c16 = bC16 + i;
            uint32_t doff = SWZ((uint32_t)(bRowS * 128 + c16 * 16));
            cpa16(sA + OFF_B + doff, bW + boff + c16 * 8, 16);
        }
    };

    float acc[4][4][4];
    #pragma unroll
    for (int a = 0; a < 4; a++)
        #pragma unroll
        for (int b = 0; b < 4; b++)
            #pragma unroll
            for (int c = 0; c < 4; c++) acc[a][b][c] = 0.f;

    issue(0, 0); CP_COMMIT();
    issue(1, 1); CP_COMMIT();

    for (int cc = 0; cc < 12; cc++) {
        int buf = cc % 3;
        if (cc + 2 < 12) {
            issue(cc + 2, (cc + 2) % 3);
            CP_COMMIT();
            CP_WAIT2();
        } else if (cc + 1 < 12) {
            CP_WAIT1();
        } else {
            CP_WAIT0();
        }
        __syncthreads();

        {
            uint32_t aB = smem_u32(smem + buf * STAGE_SZ);
            uint32_t bB = aB + OFF_B;
            #pragma unroll
            for (int k16 = 0; k16 < 4; k16++) {
                uint32_t bF[8];
                #pragma unroll
                for (int p = 0; p < 2; p++) {
                    int n = warpN * 32 + p * 16 + bRowO;
                    LDSM4(bF[4*p+0], bF[4*p+1], bF[4*p+2], bF[4*p+3],
                          bB + SWZ((uint32_t)(n * 128 + k16 * 32 + bColB)));
                }
                uint32_t aF[4][4];
                #pragma unroll
                for (int mt = 0; mt < 4; mt++) {
                    int r = warpM * 64 + mt * 16 + aRow;
                    LDSM4(aF[mt][0], aF[mt][1], aF[mt][2], aF[mt][3],
                          aB + SWZ((uint32_t)(r * 128 + k16 * 32 + aColB)));
                }
                #pragma unroll
                for (int mt = 0; mt < 4; mt++)
                    #pragma unroll
                    for (int nt = 0; nt < 4; nt++)
                        MMA16816(acc[mt][nt], aF[mt], bF[nt*2], bF[nt*2+1]);
            }
        }

        if (cc == 3) {
            // gate epilogue: sigmoid(D2 + bias) -> Gs (smem, fp16), reset acc
            #pragma unroll
            for (int mt = 0; mt < 4; mt++) {
                #pragma unroll
                for (int nt = 0; nt < 4; nt++) {
                    int gc = cbase + nt * 8 + (lane & 3) * 2;
                    float b0 = bias[gc], b1 = bias[gc + 1];
                    float g0 = 1.f / (1.f + __expf(-(acc[mt][nt][0] + b0)));
                    float g1 = 1.f / (1.f + __expf(-(acc[mt][nt][1] + b1)));
                    float g2 = 1.f / (1.f + __expf(-(acc[mt][nt][2] + b0)));
                    float g3 = 1.f / (1.f + __expf(-(acc[mt][nt][3] + b1)));
                    __half2 p01 = __floats2half2_rn(g0, g1);
                    __half2 p23 = __floats2half2_rn(g2, g3);
                    Gs[((mt * 4 + nt) * 2 + 0) * 512 + tid] = *reinterpret_cast<uint32_t*>(&p01);
                    Gs[((mt * 4 + nt) * 2 + 1) * 512 + tid] = *reinterpret_cast<uint32_t*>(&p23);
                    acc[mt][nt][0] = 0.f; acc[mt][nt][1] = 0.f;
                    acc[mt][nt][2] = 0.f; acc[mt][nt][3] = 0.f;
                }
            }
        }
        __syncthreads();
    }

    // final epilogue: out = relu(gate*D1 + (1-gate)*prev), gate from smem
    #pragma unroll
    for (int mt = 0; mt < 4; mt++) {
        #pragma unroll
        for (int nt = 0; nt < 4; nt++) {
            int gr = rbase + mt * 16 + (lane >> 2);
            int gc = cbase + nt * 8 + (lane & 3) * 2;
            uint32_t u01 = Gs[((mt * 4 + nt) * 2 + 0) * 512 + tid];
            uint32_t u23 = Gs[((mt * 4 + nt) * 2 + 1) * 512 + tid];
            float2 g01 = __half22float2(*reinterpret_cast<__half2*>(&u01));
            float2 g23 = __half22float2(*reinterpret_cast<__half2*>(&u23));
            if (gr < N_NODES) {
                float2 pv = *reinterpret_cast<const float2*>(prevh + (size_t)gr * DIM + gc);
                float2 v;
                v.x = fmaxf(g01.x * acc[mt][nt][0] + (1.f - g01.x) * pv.x, 0.f);
                v.y = fmaxf(g01.y * acc[mt][nt][1] + (1.f - g01.y) * pv.y, 0.f);
                *reinterpret_cast<float2*>(out + (size_t)gr * DIM + gc) = v;
            }
            if (gr + 8 < N_NODES) {
                float2 pv = *reinterpret_cast<const float2*>(prevh + (size_t)(gr + 8) * DIM + gc);
                float2 v;
                v.x = fmaxf(g23.x * acc[mt][nt][2] + (1.f - g23.x) * pv.x, 0.f);
                v.y = fmaxf(g23.y * acc[mt][nt][3] + (1.f - g23.y) * pv.y, 0.f);
                *reinterpret_cast<float2*>(out + (size_t)(gr + 8) * DIM + gc) = v;
            }
        }
    }
}

// ---------------------------------------------------------------------------
// 4) fixup for indeg==0 rows (compacted list, ~124 entries):
//    out = relu(sig(prev@Ws + b) * (h@Wev) + (1-sig)*prev)   (exact fp32)
// ---------------------------------------------------------------------------
__global__ void fixup_kernel(const float* __restrict__ h,
                             const float* __restrict__ Wev,
                             const float* __restrict__ Ws,
                             const float* __restrict__ prevh,
                             const float* __restrict__ bias,
                             float* __restrict__ out) {
    __shared__ float hr[DIM];
    __shared__ float pr[DIM];
    int t = threadIdx.x;
    for (int li = blockIdx.x; li < g_nfix; li += gridDim.x) {
        int n = g_list[li];
        hr[t] = h[(size_t)n * DIM + t];
        pr[t] = prevh[(size_t)n * DIM + t];
        __syncthreads();
        float accE = 0.f, accS = 0.f;
        #pragma unroll 8
        for (int k = 0; k < DIM; k++) {
            accE += hr[k] * Wev[(size_t)k * DIM + t];
            accS += pr[k] * Ws[(size_t)k * DIM + t];
        }
        float g = 1.f / (1.f + __expf(-(accS + bias[t])));
        out[(size_t)n * DIM + t] = fmaxf(g * accE + (1.f - g) * pr[t], 0.f);
        __syncthreads();
    }
}

// ---------------------------------------------------------------------------
extern "C" void kernel_launch(void* const* d_in, const int* in_sizes, int n_in,
                              void* d_out, int out_size) {
    const float* h       = (const float*)d_in[0];
    const float* prev_h  = (const float*)d_in[1];
    const float* emb_rel = (const float*)d_in[2];
    const float* norm    = (const float*)d_in[3];
    const float* w_n     = (const float*)d_in[4];
    const float* w_loop  = (const float*)d_in[5];
    const float* w_ev    = (const float*)d_in[6];
    const float* w_skip  = (const float*)d_in[7];
    const float* b_skip  = (const float*)d_in[8];
    const int*   src     = (const int*)d_in[9];
    const int*   dst     = (const int*)d_in[10];
    const int*   etype   = (const int*)d_in[11];
    float* out = (float*)d_out;

    cudaFuncSetAttribute(fused_gemm_kernel,
                         cudaFuncAttributeMaxDynamicSharedMemorySize, SMEM_TOT);

    zero_prep_kernel<<<2048, 256>>>(h, prev_h, w_n, w_loop, w_skip);   // 1

    {
        long long threads = (long long)N_EDGES * 32;
        int blocks = (int)((threads + 255) / 256);
        edge_kernel<<<blocks, 256>>>(h, emb_rel, src, dst, etype);     // 2
    }

    {
        int total4 = N_NODES * DIM / 4;
        conv_pre_kernel<<<(total4 + 255) / 256, 256>>>(norm);          // 3
    }

    {
        dim3 grid((N_NODES + 127) / 128);
        fused_gemm_kernel<<<grid, 512, SMEM_TOT>>>(prev_h, b_skip, out);  // 4 (profiled)
    }

    fixup_kernel<<<256, DIM>>>(h, w_ev, w_skip, prev_h, b_skip, out);     // 5
}

// round 12
// speedup vs baseline: 1.2968x; 1.0011x over previous
#include <cuda_runtime.h>
#include <cuda_fp16.h>
#include <math.h>
#include <stdint.h>

#define N_NODES 50000
#define N_EDGES 300000
#define DIM 256
#define N_RELS 500

// ---------------------------------------------------------------------------
// Device-global scratch (never passed from host — R1 lesson)
// ---------------------------------------------------------------------------
__device__ float  g_pre[N_NODES * DIM];    // fp32 segment-sum target (atomics)
__device__ int    g_indeg[N_NODES];
__device__ int    g_list[N_NODES];
__device__ int    g_nfix;
__device__ __half g_h16  [N_NODES * DIM];  // h, fp16
__device__ __half g_p16  [N_NODES * DIM];  // prev_h, fp16
__device__ __half g_pre16[N_NODES * DIM];  // (pre * norm), fp16
__device__ __half g_w1T[256 * 512];        // [Wn ; L]^T  (n rows, k contiguous)
__device__ __half g_w2T[256 * 256];        // Ws^T

// ---------------------------------------------------------------------------
// helpers
// ---------------------------------------------------------------------------
__device__ __forceinline__ uint32_t smem_u32(const void* p) {
    uint32_t a;
    asm("{ .reg .u64 t; cvta.to.shared.u64 t, %1; cvt.u32.u64 %0, t; }"
        : "=r"(a) : "l"(p));
    return a;
}
#define SWZ(o) ((o) ^ (((o) >> 3) & 0x70))

#define LDSM4(r0, r1, r2, r3, addr) \
    asm volatile("ldmatrix.sync.aligned.m8n8.x4.shared.b16 {%0,%1,%2,%3}, [%4];" \
                 : "=r"(r0), "=r"(r1), "=r"(r2), "=r"(r3) : "r"(addr))

#define MMA16816(c, a, b0, b1) \
    asm volatile("mma.sync.aligned.m16n8k16.row.col.f32.f16.f16.f32 " \
                 "{%0,%1,%2,%3}, {%4,%5,%6,%7}, {%8,%9}, {%0,%1,%2,%3};" \
                 : "+f"((c)[0]), "+f"((c)[1]), "+f"((c)[2]), "+f"((c)[3]) \
                 : "r"((a)[0]), "r"((a)[1]), "r"((a)[2]), "r"((a)[3]), \
                   "r"(b0), "r"(b1))

__device__ __forceinline__ void cpa16(uint32_t dst, const void* src, int sz) {
    asm volatile("cp.async.ca.shared.global [%0], [%1], 16, %2;"
                 :: "r"(dst), "l"(src), "r"(sz));
}
#define CP_COMMIT() asm volatile("cp.async.commit_group;" ::: "memory")
#define CP_WAIT2()  asm volatile("cp.async.wait_group 2;" ::: "memory")
#define CP_WAIT1()  asm volatile("cp.async.wait_group 1;" ::: "memory")
#define CP_WAIT0()  asm volatile("cp.async.wait_group 0;" ::: "memory")

// smem: [A 16K][B 32K] x 3 stages = 144 KB, then gate store 64 KB = 208 KB
#define OFF_B    16384
#define STAGE_SZ 49152
#define OFF_GS   (3 * STAGE_SZ)
#define SMEM_TOT (3 * STAGE_SZ + 65536)

// ---------------------------------------------------------------------------
// 1) merged: zero g_pre/g_indeg/g_nfix, convert h & prev_h -> fp16, prep W
// ---------------------------------------------------------------------------
__global__ void zero_prep_kernel(const float* __restrict__ h,
                                 const float* __restrict__ prev,
                                 const float* __restrict__ Wn,
                                 const float* __restrict__ L,
                                 const float* __restrict__ Ws) {
    int i = blockIdx.x * blockDim.x + threadIdx.x;
    const int total4 = N_NODES * DIM / 4;
    float4 z = make_float4(0.f, 0.f, 0.f, 0.f);
    for (int idx = i; idx < total4; idx += gridDim.x * blockDim.x) {
        reinterpret_cast<float4*>(g_pre)[idx] = z;
        float4 hv = reinterpret_cast<const float4*>(h)[idx];
        float4 pv = reinterpret_cast<const float4*>(prev)[idx];
        __half2 hh0 = __floats2half2_rn(hv.x, hv.y);
        __half2 hh1 = __floats2half2_rn(hv.z, hv.w);
        __half2 ph0 = __floats2half2_rn(pv.x, pv.y);
        __half2 ph1 = __floats2half2_rn(pv.z, pv.w);
        reinterpret_cast<uint2*>(g_h16)[idx] =
            make_uint2(*reinterpret_cast<uint32_t*>(&hh0), *reinterpret_cast<uint32_t*>(&hh1));
        reinterpret_cast<uint2*>(g_p16)[idx] =
            make_uint2(*reinterpret_cast<uint32_t*>(&ph0), *reinterpret_cast<uint32_t*>(&ph1));
    }
    if (i < N_NODES) g_indeg[i] = 0;
    if (i == 0) g_nfix = 0;
    if (i < 256 * 512) {
        int n = i >> 9;
        int k = i & 511;
        float w = (k < 256) ? Wn[k * 256 + n] : L[(k - 256) * 256 + n];
        g_w1T[i] = __float2half_rn(w);
    }
    if (i < 256 * 256) {
        int n = i >> 8;
        int k = i & 255;
        g_w2T[i] = __float2half_rn(Ws[k * 256 + n]);
    }
}

// ---------------------------------------------------------------------------
// 2) edge scatter: pre[dst] += h[src] + emb_rel[etype];  indeg[dst] += 1
// ---------------------------------------------------------------------------
__global__ void edge_kernel(const float* __restrict__ h,
                            const float* __restrict__ emb,
                            const int*   __restrict__ src,
                            const int*   __restrict__ dst,
                            const int*   __restrict__ etype) {
    long long tid = (long long)blockIdx.x * blockDim.x + threadIdx.x;
    int e = (int)(tid >> 5);
    int j = (int)(tid & 31);
    if (e >= N_EDGES) return;
    int s = src[e];
    int d = dst[e];
    int r = etype[e];
    if (j == 0) atomicAdd(&g_indeg[d], 1);

    const float4* hp = reinterpret_cast<const float4*>(h   + (size_t)s * DIM);
    const float4* ep = reinterpret_cast<const float4*>(emb + (size_t)r * DIM);
    #pragma unroll
    for (int q = 0; q < 2; q++) {
        int jj = j + q * 32;
        float4 hv = hp[jj];
        float4 ev = ep[jj];
        float4 v = make_float4(hv.x + ev.x, hv.y + ev.y, hv.z + ev.z, hv.w + ev.w);
        float* p = g_pre + (size_t)d * DIM + (size_t)jj * 4;
        asm volatile("red.global.add.v4.f32 [%0], {%1, %2, %3, %4};"
                     :: "l"(p), "f"(v.x), "f"(v.y), "f"(v.z), "f"(v.w) : "memory");
    }
}

// ---------------------------------------------------------------------------
// 2b) convert (pre * norm) -> fp16 + build compact indeg==0 list
// ---------------------------------------------------------------------------
__global__ void conv_pre_kernel(const float* __restrict__ norm) {
    int idx = blockIdx.x * blockDim.x + threadIdx.x;
    const int total4 = N_NODES * DIM / 4;
    if (idx >= total4) return;
    int row = idx >> 6;
    if ((idx & 63) == 0 && g_indeg[row] == 0) {
        int slot = atomicAdd(&g_nfix, 1);
        g_list[slot] = row;
    }
    float nm = __ldg(norm + row);
    float4 v = reinterpret_cast<const float4*>(g_pre)[idx];
    v.x *= nm; v.y *= nm; v.z *= nm; v.w *= nm;
    __half2 h0 = __floats2half2_rn(v.x, v.y);
    __half2 h1 = __floats2half2_rn(v.z, v.w);
    reinterpret_cast<uint2*>(g_pre16)[idx] =
        make_uint2(*reinterpret_cast<uint32_t*>(&h0), *reinterpret_cast<uint32_t*>(&h1));
}

// ---------------------------------------------------------------------------
// 3) pipelined fused GEMM — CTA tile 128 rows x 256 cols, 512 threads,
//    3-stage cp.async; gate tile kept in SMEM (no DRAM round-trip).
//    chunks 0-3 : gate  D2 = prev @ Ws^T            (K=256)
//    chunks 4-11: main  D1 = [pre*norm|h] @ [Wn;L]^T (K=512)
// ---------------------------------------------------------------------------
__global__ __launch_bounds__(512, 1)
void fused_gemm_kernel(const float* __restrict__ prevh,
                       const float* __restrict__ bias,
                       float* __restrict__ out) {
    extern __shared__ char smem[];
    uint32_t* Gs = reinterpret_cast<uint32_t*>(smem + OFF_GS);  // [32][512]

    const int tid  = threadIdx.x;
    const int lane = tid & 31;
    const int wid  = tid >> 5;
    const int warpM = wid >> 3;          // 0..1
    const int warpN = wid & 7;           // 0..7
    const int row0  = blockIdx.x * 128;

    // staging coords
    const int aRowS = tid >> 2;          // 0..127 (A rows), 2 granules each
    const int aC16  = (tid & 3) * 2;
    const int bRowS = tid >> 1;          // 0..255 (B n-rows), 4 granules each
    const int bC16  = (tid & 1) * 4;

    // ldmatrix lane-address components
    const int aRow  = (lane & 7) + ((lane >> 3) & 1) * 8;
    const int aColB = ((lane >> 4) & 1) * 16;
    const int bRowO = ((lane >> 4) & 1) * 8 + (lane & 7);
    const int bColB = ((lane >> 3) & 1) * 16;

    const int rbase = row0 + warpM * 64;
    const int cbase = warpN * 32;

    auto issue = [&](int cc, int buf) {
        uint32_t sA = smem_u32(smem + buf * STAGE_SZ);
        const __half *aS, *bW;
        int kbA, kbB, KB;
        if (cc < 4) {
            aS = g_p16; kbA = cc * 64; bW = g_w2T; kbB = cc * 64; KB = 256;
        } else {
            int d = cc - 4;
            aS = (d < 4) ? g_pre16 : g_h16;
            kbA = (d & 3) * 64;
            bW = g_w1T; kbB = d * 64; KB = 512;
        }
        int grow = row0 + aRowS;
        int asz = (grow < N_NODES) ? 16 : 0;
        size_t aoff = (size_t)grow * DIM + kbA;
        #pragma unroll
        for (int i = 0; i < 2; i++) {
            int c16 = aC16 + i;
            uint32_t doff = SWZ((uint32_t)(aRowS * 128 + c16 * 16));
            cpa16(sA + doff, aS + aoff + c16 * 8, asz);
        }
        size_t boff = (size_t)bRowS * KB + kbB;
        #pragma unroll
        for (int i = 0; i < 4; i++) {
            int c16 = bC16 + i;
            uint32_t doff = SWZ((uint32_t)(bRowS * 128 + c16 * 16));
            cpa16(sA + OFF_B + doff, bW + boff + c16 * 8, 16);
        }
    };

    float acc[4][4][4];
    #pragma unroll
    for (int a = 0; a < 4; a++)
        #pragma unroll
        for (int b = 0; b < 4; b++)
            #pragma unroll
            for (int c = 0; c < 4; c++) acc[a][b][c] = 0.f;

    issue(0, 0); CP_COMMIT();
    issue(1, 1); CP_COMMIT();

    for (int cc = 0; cc < 12; cc++) {
        int buf = cc % 3;
        if (cc + 2 < 12) {
            issue(cc + 2, (cc + 2) % 3);
            CP_COMMIT();
            CP_WAIT2();
        } else if (cc + 1 < 12) {
            CP_WAIT1();
        } else {
            CP_WAIT0();
        }
        __syncthreads();

        {
            uint32_t aB = smem_u32(smem + buf * STAGE_SZ);
            uint32_t bB = aB + OFF_B;
            #pragma unroll
            for (int k16 = 0; k16 < 4; k16++) {
                uint32_t bF[8];
                #pragma unroll
                for (int p = 0; p < 2; p++) {
                    int n = warpN * 32 + p * 16 + bRowO;
                    LDSM4(bF[4*p+0], bF[4*p+1], bF[4*p+2], bF[4*p+3],
                          bB + SWZ((uint32_t)(n * 128 + k16 * 32 + bColB)));
                }
                uint32_t aF[4][4];
                #pragma unroll
                for (int mt = 0; mt < 4; mt++) {
                    int r = warpM * 64 + mt * 16 + aRow;
                    LDSM4(aF[mt][0], aF[mt][1], aF[mt][2], aF[mt][3],
                          aB + SWZ((uint32_t)(r * 128 + k16 * 32 + aColB)));
                }
                #pragma unroll
                for (int mt = 0; mt < 4; mt++)
                    #pragma unroll
                    for (int nt = 0; nt < 4; nt++)
                        MMA16816(acc[mt][nt], aF[mt], bF[nt*2], bF[nt*2+1]);
            }
        }

        if (cc == 3) {
            // gate epilogue: sigmoid(D2 + bias) -> Gs (smem, fp16), reset acc
            #pragma unroll
            for (int mt = 0; mt < 4; mt++) {
                #pragma unroll
                for (int nt = 0; nt < 4; nt++) {
                    int gc = cbase + nt * 8 + (lane & 3) * 2;
                    float b0 = bias[gc], b1 = bias[gc + 1];
                    float g0 = 1.f / (1.f + __expf(-(acc[mt][nt][0] + b0)));
                    float g1 = 1.f / (1.f + __expf(-(acc[mt][nt][1] + b1)));
                    float g2 = 1.f / (1.f + __expf(-(acc[mt][nt][2] + b0)));
                    float g3 = 1.f / (1.f + __expf(-(acc[mt][nt][3] + b1)));
                    __half2 p01 = __floats2half2_rn(g0, g1);
                    __half2 p23 = __floats2half2_rn(g2, g3);
                    Gs[((mt * 4 + nt) * 2 + 0) * 512 + tid] = *reinterpret_cast<uint32_t*>(&p01);
                    Gs[((mt * 4 + nt) * 2 + 1) * 512 + tid] = *reinterpret_cast<uint32_t*>(&p23);
                    acc[mt][nt][0] = 0.f; acc[mt][nt][1] = 0.f;
                    acc[mt][nt][2] = 0.f; acc[mt][nt][3] = 0.f;
                }
            }
        }
        __syncthreads();
    }

    // final epilogue: out = relu(gate*D1 + (1-gate)*prev), gate from smem
    #pragma unroll
    for (int mt = 0; mt < 4; mt++) {
        #pragma unroll
        for (int nt = 0; nt < 4; nt++) {
            int gr = rbase + mt * 16 + (lane >> 2);
            int gc = cbase + nt * 8 + (lane & 3) * 2;
            uint32_t u01 = Gs[((mt * 4 + nt) * 2 + 0) * 512 + tid];
            uint32_t u23 = Gs[((mt * 4 + nt) * 2 + 1) * 512 + tid];
            float2 g01 = __half22float2(*reinterpret_cast<__half2*>(&u01));
            float2 g23 = __half22float2(*reinterpret_cast<__half2*>(&u23));
            if (gr < N_NODES) {
                float2 pv = *reinterpret_cast<const float2*>(prevh + (size_t)gr * DIM + gc);
                float2 v;
                v.x = fmaxf(g01.x * acc[mt][nt][0] + (1.f - g01.x) * pv.x, 0.f);
                v.y = fmaxf(g01.y * acc[mt][nt][1] + (1.f - g01.y) * pv.y, 0.f);
                *reinterpret_cast<float2*>(out + (size_t)gr * DIM + gc) = v;
            }
            if (gr + 8 < N_NODES) {
                float2 pv = *reinterpret_cast<const float2*>(prevh + (size_t)(gr + 8) * DIM + gc);
                float2 v;
                v.x = fmaxf(g23.x * acc[mt][nt][2] + (1.f - g23.x) * pv.x, 0.f);
                v.y = fmaxf(g23.y * acc[mt][nt][3] + (1.f - g23.y) * pv.y, 0.f);
                *reinterpret_cast<float2*>(out + (size_t)(gr + 8) * DIM + gc) = v;
            }
        }
    }
}

// ---------------------------------------------------------------------------
// 4) fixup for indeg==0 rows (compacted list, ~124 entries):
//    out = relu(sig(prev@Ws + b) * (h@Wev) + (1-sig)*prev)   (exact fp32)
// ---------------------------------------------------------------------------
__global__ void fixup_kernel(const float* __restrict__ h,
                             const float* __restrict__ Wev,
                             const float* __restrict__ Ws,
                             const float* __restrict__ prevh,
                             const float* __restrict__ bias,
                             float* __restrict__ out) {
    __shared__ float hr[DIM];
    __shared__ float pr[DIM];
    int t = threadIdx.x;
    for (int li = blockIdx.x; li < g_nfix; li += gridDim.x) {
        int n = g_list[li];
        hr[t] = h[(size_t)n * DIM + t];
        pr[t] = prevh[(size_t)n * DIM + t];
        __syncthreads();
        float accE = 0.f, accS = 0.f;
        #pragma unroll 8
        for (int k = 0; k < DIM; k++) {
            accE += hr[k] * Wev[(size_t)k * DIM + t];
            accS += pr[k] * Ws[(size_t)k * DIM + t];
        }
        float g = 1.f / (1.f + __expf(-(accS + bias[t])));
        out[(size_t)n * DIM + t] = fmaxf(g * accE + (1.f - g) * pr[t], 0.f);
        __syncthreads();
    }
}

// ---------------------------------------------------------------------------
extern "C" void kernel_launch(void* const* d_in, const int* in_sizes, int n_in,
                              void* d_out, int out_size) {
    const float* h       = (const float*)d_in[0];
    const float* prev_h  = (const float*)d_in[1];
    const float* emb_rel = (const float*)d_in[2];
    const float* norm    = (const float*)d_in[3];
    const float* w_n     = (const float*)d_in[4];
    const float* w_loop  = (const float*)d_in[5];
    const float* w_ev    = (const float*)d_in[6];
    const float* w_skip  = (const float*)d_in[7];
    const float* b_skip  = (const float*)d_in[8];
    const int*   src     = (const int*)d_in[9];
    const int*   dst     = (const int*)d_in[10];
    const int*   etype   = (const int*)d_in[11];
    float* out = (float*)d_out;

    cudaFuncSetAttribute(fused_gemm_kernel,
                         cudaFuncAttributeMaxDynamicSharedMemorySize, SMEM_TOT);

    zero_prep_kernel<<<2048, 256>>>(h, prev_h, w_n, w_loop, w_skip);   // 1

    {
        long long threads = (long long)N_EDGES * 32;
        int blocks = (int)((threads + 255) / 256);
        edge_kernel<<<blocks, 256>>>(h, emb_rel, src, dst, etype);     // 2
    }

    {
        int total4 = N_NODES * DIM / 4;
        conv_pre_kernel<<<(total4 + 255) / 256, 256>>>(norm);          // 3
    }

    {
        dim3 grid((N_NODES + 127) / 128);
        fused_gemm_kernel<<<grid, 512, SMEM_TOT>>>(prev_h, b_skip, out);  // 4 (profiled)
    }

    fixup_kernel<<<256, DIM>>>(h, w_ev, w_skip, prev_h, b_skip, out);     // 5
}